// round 14
// baseline (speedup 1.0000x reference)
#include <cuda_runtime.h>
#include <cstdint>

// ---------------------------------------------------------------------------
// BVP Helmholtz residual via 2nd-order jet propagation on mma.sync s8 IMMA
// (m16n8k32, 2-level int8 quantization, 3 integer passes, runtime per-row
// scales). 512 thr, M=64 (12 samples/CTA), 16 warps x (mt4 x nt2), zero-sync
// mainloop with per-warp private double-buffered B pipelines (cp.async).
// D = asc_m * wsc_n * (acc_hi + acc_mid/128) fixup in the epilogue.
// ---------------------------------------------------------------------------

#define HD 256
#define SB 12
#define AROWI 272          // A int8 row stride (bytes)
#define AL 17408           // 64*272, level stride
#define DROW 260           // D row stride (floats)
#define BROWI 48           // B slice row stride (bytes, 16-aligned)
#define BLVL 768           // 16 rows * 48
#define BSTGI 1536         // 2 levels
#define BTOTI 3072         // 2 stages

#define D_OFF 0            // 64*1040 = 66560
#define A_OFF 66560        // 2*17408 = 34816
#define B_OFF 101376       // 16*3072 = 49152
#define XYZF_OFF 150528    // 192
#define PART_OFF 150720    // 1536
#define RR_OFF 152256      // 64*8*4 = 2048
#define ASC_OFF 154304     // 256
#define AINV_OFF 154560    // 256
#define SMEM_BYTES 154816

// quantized weights: [layer][level][n][k], and per-n scales
__device__ __align__(16) signed char Wq[2][2][HD][HD];
__device__ float wsc_g[2 * HD];

__global__ __launch_bounds__(64)
void prep_w(const float* __restrict__ W2, const float* __restrict__ W3)
{
    int layer = blockIdx.x >> 8, n = blockIdx.x & 255;
    const float* W = layer ? W3 : W2;
    int t = threadIdx.x;                       // 0..63, 4 k each
    float4 v = *(const float4*)(W + n * HD + t * 4);
    float mx = fmaxf(fmaxf(fabsf(v.x), fabsf(v.y)),
                     fmaxf(fabsf(v.z), fabsf(v.w)));
    #pragma unroll
    for (int o = 16; o; o >>= 1)
        mx = fmaxf(mx, __shfl_xor_sync(0xFFFFFFFFu, mx, o));
    __shared__ float pm[2];
    if ((t & 31) == 0) pm[t >> 5] = mx;
    __syncthreads();
    mx = fmaxf(pm[0], pm[1]);
    float inv = mx > 0.f ? 127.0f / mx : 0.f;
    float tv[4] = {v.x, v.y, v.z, v.w};
    signed char q1[4], q2[4];
    #pragma unroll
    for (int j = 0; j < 4; ++j) {
        float tt = tv[j] * inv;
        int a = __float2int_rn(tt);
        q1[j] = (signed char)a;
        q2[j] = (signed char)__float2int_rn((tt - (float)a) * 128.0f);
    }
    *(char4*)&Wq[layer][0][n][t * 4] = make_char4(q1[0], q1[1], q1[2], q1[3]);
    *(char4*)&Wq[layer][1][n][t * 4] = make_char4(q2[0], q2[1], q2[2], q2[3]);
    if (t == 0) wsc_g[layer * HD + n] = mx * (1.0f / 127.0f);
}

__device__ __forceinline__ uint32_t smem_u32(const void* p) {
    uint32_t a;
    asm("{ .reg .u64 t; cvta.to.shared.u64 t, %1; cvt.u32.u64 %0, t; }"
        : "=r"(a) : "l"(p));
    return a;
}
__device__ __forceinline__ void ldsm4(uint32_t* r, uint32_t a) {
    asm volatile("ldmatrix.sync.aligned.m8n8.x4.shared.b16 {%0,%1,%2,%3}, [%4];"
                 : "=r"(r[0]), "=r"(r[1]), "=r"(r[2]), "=r"(r[3]) : "r"(a));
}
__device__ __forceinline__ void ldsm2(uint32_t* r, uint32_t a) {
    asm volatile("ldmatrix.sync.aligned.m8n8.x2.shared.b16 {%0,%1}, [%2];"
                 : "=r"(r[0]), "=r"(r[1]) : "r"(a));
}
__device__ __forceinline__ void mma_s8(int* c, const uint32_t* a,
                                       const uint32_t* b) {
    asm volatile("mma.sync.aligned.m16n8k32.row.col.s32.s8.s8.s32 "
                 "{%0,%1,%2,%3}, {%4,%5,%6,%7}, {%8,%9}, {%0,%1,%2,%3};"
                 : "+r"(c[0]), "+r"(c[1]), "+r"(c[2]), "+r"(c[3])
                 : "r"(a[0]), "r"(a[1]), "r"(a[2]), "r"(a[3]),
                   "r"(b[0]), "r"(b[1]));
}
__device__ __forceinline__ void cp16(uint32_t sa, const void* ga) {
    asm volatile("cp.async.cg.shared.global [%0], [%1], 16;"
                 :: "r"(sa), "l"(__cvta_generic_to_global(ga)) : "memory");
}
#define CP_COMMIT() asm volatile("cp.async.commit_group;" ::: "memory")
#define CP_WAIT(n)  asm volatile("cp.async.wait_group %0;" :: "n"(n) : "memory")

__device__ __forceinline__ float ftanh(float u) {
    float e = __expf(2.0f * u);
    return 1.0f - __fdividef(2.0f, e + 1.0f);
}

__global__ __launch_bounds__(512, 1)
void bvp_imma_kernel(const float* __restrict__ gx, const float* __restrict__ gy,
                     const float* __restrict__ gz, const float* __restrict__ gf,
                     const float* __restrict__ W1, const float* __restrict__ b1,
                     const float* __restrict__ b2, const float* __restrict__ b3,
                     const float* __restrict__ W4, const float* __restrict__ b4,
                     float* __restrict__ out, int N)
{
    extern __shared__ char sm[];
    const uint32_t smb = smem_u32(sm);
    float* Dst   = (float*)(sm + D_OFF);
    float* xyzf  = (float*)(sm + XYZF_OFF);
    float* part  = (float*)(sm + PART_OFF);   // [12][8][4]
    float* rr    = (float*)(sm + RR_OFF);     // [64][8]
    float* ascS  = (float*)(sm + ASC_OFF);    // [64]
    float* ainvS = (float*)(sm + AINV_OFF);   // [64]

    const int tid = threadIdx.x;
    const int wid = tid >> 5;
    const int lid = tid & 31;
    const int n0w = wid << 4;                 // warp n-slice: 16 cols
    const int n0  = blockIdx.x * SB;
    const int sg  = tid >> 8;                 // sample group 0/1
    const int nn  = tid & 255;                // column

    const float CX = (float)((0.5 * 0.6) * (0.5 * 0.6));
    const float CY = (float)((0.7 * 0.6) * (0.7 * 0.6));
    const float CZ = (float)((0.7 * 0.5) * (0.7 * 0.5));

    const uint32_t myb = smb + B_OFF + wid * BTOTI;
    auto issue_chunk = [&](int gi) {          // gi in [0,16): layer*8 + kc
        int L = gi >> 3, kc = gi & 7;
        uint32_t base = myb + (gi & 1) * BSTGI;
        #pragma unroll
        for (int j = 0; j < 2; ++j) {
            int idx = lid + (j << 5);         // 0..63
            int lvl = idx >> 5;
            int r   = (idx >> 1) & 15;
            int hf  = idx & 1;
            cp16(base + lvl * BLVL + r * BROWI + hf * 16,
                 &Wq[L][lvl][n0w + r][kc * 32 + hf * 16]);
        }
        CP_COMMIT();
    };

    // rowmax + 2-level int8 quantize of the 30 jet values each thread owns
    auto quantize_rows = [&](float* vv) {
        #pragma unroll
        for (int i = 0; i < 30; ++i) {
            float av = fabsf(vv[i]);
            #pragma unroll
            for (int o = 16; o; o >>= 1)
                av = fmaxf(av, __shfl_xor_sync(0xFFFFFFFFu, av, o));
            if (lid == 0) rr[(sg * 30 + i) * 8 + (wid & 7)] = av;
        }
        __syncthreads();
        if (nn < 30) {
            int m = sg * 30 + nn;
            float mx = 0.f;
            #pragma unroll
            for (int j = 0; j < 8; ++j) mx = fmaxf(mx, rr[m * 8 + j]);
            ascS[m]  = mx * (1.0f / 127.0f);
            ainvS[m] = mx > 0.f ? 127.0f / mx : 0.f;
        }
        __syncthreads();
        #pragma unroll
        for (int i = 0; i < 30; ++i) {
            int m = sg * 30 + i;
            float t = vv[i] * ainvS[m];
            int q1 = __float2int_rn(t);
            int q2 = __float2int_rn((t - (float)q1) * 128.0f);
            *(signed char*)(sm + A_OFF + m * AROWI + nn) = (signed char)q1;
            *(signed char*)(sm + A_OFF + AL + m * AROWI + nn) = (signed char)q2;
        }
    };

    // prefetch first two B chunks of layer 0
    issue_chunk(0);
    issue_chunk(1);

    // init: coords, zero pad rows 60..63 (both levels), asc pads
    if (tid < 48) {
        int ss = tid >> 2, w = tid & 3;
        int n = n0 + ss; if (n >= N) n = N - 1;
        const float* p = (w == 0) ? gx : (w == 1) ? gy : (w == 2) ? gz : gf;
        xyzf[tid] = p[n];
    }
    {
        int lvl = tid >> 8, r = (tid >> 6) & 3, wd = tid & 63;
        *(uint32_t*)(sm + A_OFF + lvl * AL + (60 + r) * AROWI + wd * 4) = 0u;
        if (tid < 4) ascS[60 + tid] = 0.f;
    }
    __syncthreads();

    // ---- layer 1: 4 -> 256, jets analytically, quantize ---------------------
    {
        float vv[30];
        float4 w = *(const float4*)(W1 + nn * 4);
        float bb = b1[nn];
        float gq = CX * w.x * w.x + CY * w.y * w.y + CZ * w.z * w.z;
        #pragma unroll
        for (int sl = 0; sl < 6; ++sl) {
            int s = sg * 6 + sl;
            float u = fmaf(w.x, xyzf[s * 4 + 0], fmaf(w.y, xyzf[s * 4 + 1],
                      fmaf(w.z, xyzf[s * 4 + 2], fmaf(w.w, xyzf[s * 4 + 3],
                      bb))));
            float yv = ftanh(u);
            float sgm = fmaf(-yv, yv, 1.0f);
            vv[sl * 5 + 0] = yv;
            vv[sl * 5 + 1] = sgm * w.x;
            vv[sl * 5 + 2] = sgm * w.y;
            vv[sl * 5 + 3] = sgm * w.z;
            vv[sl * 5 + 4] = -2.0f * yv * sgm * gq;
        }
        quantize_rows(vv);
    }
    __syncthreads();

    const int g = lid >> 2, cc = (lid & 3) << 1;

    // ---- hidden layers 2,3 ---------------------------------------------------
    #pragma unroll 1
    for (int L = 0; L < 2; ++L) {
        int acch[4][2][4], accm[4][2][4];
        #pragma unroll
        for (int mt = 0; mt < 4; ++mt)
            #pragma unroll
            for (int nt = 0; nt < 2; ++nt)
                #pragma unroll
                for (int r = 0; r < 4; ++r) {
                    acch[mt][nt][r] = 0; accm[mt][nt][r] = 0;
                }

        #pragma unroll 1
        for (int kc = 0; kc < 8; ++kc) {      // k32 chunks
            int gi = (L << 3) | kc;
            if (gi == 15) { CP_WAIT(0); } else { CP_WAIT(1); }
            uint32_t bbase = myb + (gi & 1) * BSTGI;

            uint32_t b1f[2][2], b2f[2][2];
            #pragma unroll
            for (int nt = 0; nt < 2; ++nt) {
                uint32_t ba = bbase + ((nt << 3) + (lid & 7)) * BROWI +
                              (lid & 8) * 2;
                ldsm2(b1f[nt], ba);
                ldsm2(b2f[nt], ba + BLVL);
            }
            #pragma unroll
            for (int mt = 0; mt < 4; ++mt) {
                uint32_t aa = smb + A_OFF + ((mt << 4) + (lid & 15)) * AROWI +
                              kc * 32 + ((lid >> 4) << 4);
                uint32_t a1f[4], a2f[4];
                ldsm4(a1f, aa);
                ldsm4(a2f, aa + AL);
                #pragma unroll
                for (int nt = 0; nt < 2; ++nt) {
                    mma_s8(acch[mt][nt], a1f, b1f[nt]);   // a1*w1
                    mma_s8(accm[mt][nt], a1f, b2f[nt]);   // a1*w2
                    mma_s8(accm[mt][nt], a2f, b1f[nt]);   // a2*w1
                }
            }
            if (gi + 2 < 16) issue_chunk(gi + 2);
        }

        // ---- D fixup write: asc_m * wsc_n * (hi + mid/128) -------------------
        float wv[2][2];
        #pragma unroll
        for (int nt = 0; nt < 2; ++nt) {
            wv[nt][0] = wsc_g[L * HD + n0w + (nt << 3) + cc];
            wv[nt][1] = wsc_g[L * HD + n0w + (nt << 3) + cc + 1];
        }
        #pragma unroll
        for (int mt = 0; mt < 4; ++mt) {
            float amA = ascS[(mt << 4) + g];
            float amB = ascS[(mt << 4) + g + 8];
            #pragma unroll
            for (int nt = 0; nt < 2; ++nt) {
                int nc = n0w + (nt << 3) + cc;
                Dst[((mt << 4) + g) * DROW + nc] =
                    amA * wv[nt][0] * ((float)acch[mt][nt][0] +
                                       (float)accm[mt][nt][0] * 0.0078125f);
                Dst[((mt << 4) + g) * DROW + nc + 1] =
                    amA * wv[nt][1] * ((float)acch[mt][nt][1] +
                                       (float)accm[mt][nt][1] * 0.0078125f);
                Dst[((mt << 4) + g + 8) * DROW + nc] =
                    amB * wv[nt][0] * ((float)acch[mt][nt][2] +
                                       (float)accm[mt][nt][2] * 0.0078125f);
                Dst[((mt << 4) + g + 8) * DROW + nc + 1] =
                    amB * wv[nt][1] * ((float)acch[mt][nt][3] +
                                       (float)accm[mt][nt][3] * 0.0078125f);
            }
        }
        __syncthreads();   // MMA A-reads done + D visible

        // ---- activation epilogue ---------------------------------------------
        if (L == 0) {
            float vv[30];
            float bn = b2[nn];
            #pragma unroll
            for (int sl = 0; sl < 6; ++sl) {
                int s = sg * 6 + sl, mr = s * 5;
                float u  = Dst[(mr + 0) * DROW + nn] + bn;
                float tx = Dst[(mr + 1) * DROW + nn];
                float ty = Dst[(mr + 2) * DROW + nn];
                float tz = Dst[(mr + 3) * DROW + nn];
                float qa = Dst[(mr + 4) * DROW + nn];
                float yv = ftanh(u);
                float sgm = fmaf(-yv, yv, 1.0f);
                float gq = CX * tx * tx + CY * ty * ty + CZ * tz * tz;
                vv[sl * 5 + 0] = yv;
                vv[sl * 5 + 1] = sgm * tx;
                vv[sl * 5 + 2] = sgm * ty;
                vv[sl * 5 + 3] = sgm * tz;
                vv[sl * 5 + 4] = fmaf(sgm, qa, -2.0f * yv * sgm * gq);
            }
            quantize_rows(vv);
            __syncthreads();
        } else {
            float bn  = b3[nn];
            float w40 = W4[nn], w41 = W4[HD + nn];
            #pragma unroll 1
            for (int sl = 0; sl < 6; ++sl) {
                int s = sg * 6 + sl, mr = s * 5;
                float u  = Dst[(mr + 0) * DROW + nn] + bn;
                float tx = Dst[(mr + 1) * DROW + nn];
                float ty = Dst[(mr + 2) * DROW + nn];
                float tz = Dst[(mr + 3) * DROW + nn];
                float qa = Dst[(mr + 4) * DROW + nn];
                float yv = ftanh(u);
                float sgm = fmaf(-yv, yv, 1.0f);
                float gq = CX * tx * tx + CY * ty * ty + CZ * tz * tz;
                float qn = fmaf(sgm, qa, -2.0f * yv * sgm * gq);
                float v0 = w40 * yv, v1 = w41 * yv;
                float v2 = w40 * qn, v3 = w41 * qn;
                #pragma unroll
                for (int o = 16; o; o >>= 1) {
                    v0 += __shfl_xor_sync(0xFFFFFFFFu, v0, o);
                    v1 += __shfl_xor_sync(0xFFFFFFFFu, v1, o);
                    v2 += __shfl_xor_sync(0xFFFFFFFFu, v2, o);
                    v3 += __shfl_xor_sync(0xFFFFFFFFu, v3, o);
                }
                if (lid == 0) {
                    float* pp = part + (s * 8 + (wid & 7)) * 4;
                    pp[0] = v0; pp[1] = v1; pp[2] = v2; pp[3] = v3;
                }
            }
            __syncthreads();
        }
    }

    // ---- residual output -----------------------------------------------------
    if (tid < SB) {
        int n = n0 + tid;
        if (n < N) {
            float P0 = 0.f, P1 = 0.f, Q0 = 0.f, Q1 = 0.f;
            #pragma unroll
            for (int w = 0; w < 8; ++w) {
                const float* pp = part + (tid * 8 + w) * 4;
                P0 += pp[0]; P1 += pp[1]; Q0 += pp[2]; Q1 += pp[3];
            }
            P0 += b4[0]; P1 += b4[1];
            float fs = xyzf[tid * 4 + 3];
            float kw = 6.283185307179586f * fmaf(fs, 500.0f, 100.0f) / 343.0f;
            float kx = 0.21f * kw;
            float K2 = kx * kx;
            out[n]     = 2.0f * Q0 + K2 * fmaf(2.0f, P0, 0.1f);
            out[N + n] = 1.5f * Q1 + K2 * fmaf(1.5f, P1, -0.05f);
        }
    }
}

extern "C" void kernel_launch(void* const* d_in, const int* in_sizes, int n_in,
                              void* d_out, int out_size)
{
    const float* x  = (const float*)d_in[0];
    const float* y  = (const float*)d_in[1];
    const float* z  = (const float*)d_in[2];
    const float* f  = (const float*)d_in[3];
    const float* W1 = (const float*)d_in[4];
    const float* b1 = (const float*)d_in[5];
    const float* W2 = (const float*)d_in[6];
    const float* b2 = (const float*)d_in[7];
    const float* W3 = (const float*)d_in[8];
    const float* b3 = (const float*)d_in[9];
    const float* W4 = (const float*)d_in[10];
    const float* b4 = (const float*)d_in[11];
    float* out = (float*)d_out;

    int N = in_sizes[0];
    prep_w<<<512, 64>>>(W2, W3);

    cudaFuncSetAttribute(bvp_imma_kernel,
                         cudaFuncAttributeMaxDynamicSharedMemorySize,
                         SMEM_BYTES);
    int blocks = (N + SB - 1) / SB;
    bvp_imma_kernel<<<blocks, 512, SMEM_BYTES>>>(x, y, z, f, W1, b1, b2, b3,
                                                 W4, b4, out, N);
}

// round 15
// speedup vs baseline: 2.6029x; 2.6029x over previous
#include <cuda_runtime.h>
#include <cuda_bf16.h>
#include <cstdint>

// ---------------------------------------------------------------------------
// BVP Helmholtz residual via 2nd-order jet propagation on mma.sync bf16 HMMA
// (3-pass hi/lo split). Round 15: M=80 (= 5 x m16, ZERO pad waste, 16
// samples/CTA -> 6.25% fewer HMMAs), 512 thr / 16 warps each mt5 x nt2 with
// private zero-sync cp.async B pipelines (16-row slices, k16, 2-stage).
// B hi/lo fragments fetched by ONE ldsm4; epilogues use column-pair packing
// (LDS.64 reads, 32-bit packed bf16-pair stores). D aliases dead A rows.
// ---------------------------------------------------------------------------

#define HD 256
#define SB 16              // samples per CTA (80 jet rows, M=80)
#define MROWS 80
#define AROW 1040          // A row bytes: hi[0,512) pad lo[528,1040) == D row
#define DROW 260           // D row stride in floats (= 1040 B)
#define BROW 80            // B slice row: hi k16 (32B) + lo k16 (32B) + pad
#define BSTG 1280          // 16 rows * 80 = one stage of one warp's slice
#define BTOT 2560          // 2 stages

#define A_OFF 0
#define B_OFF 83200        // 80*1040
#define XYZF_OFF 124160    // B region = 16 warps * 2560 = 40960
#define PART_OFF 124416    // 16*8*4 floats = 2048 B
#define SMEM_BYTES 126464

// prepped weights: [layer][split hi/lo][n][k] bf16
__device__ __align__(16) __nv_bfloat16 Wbf[2][2][HD][HD];

__global__ __launch_bounds__(256)
void prep_weights(const float* __restrict__ W2, const float* __restrict__ W3)
{
    int t = blockIdx.x * 256 + threadIdx.x;      // 131072
    int layer = t >> 16, n = (t >> 8) & 255, k = t & 255;
    float w = (layer ? W3 : W2)[n * HD + k];
    __nv_bfloat16 h = __float2bfloat16(w);
    __nv_bfloat16 l = __float2bfloat16(w - __bfloat162float(h));
    Wbf[layer][0][n][k] = h;
    Wbf[layer][1][n][k] = l;
}

__device__ __forceinline__ uint32_t smem_u32(const void* p) {
    uint32_t a;
    asm("{ .reg .u64 t; cvta.to.shared.u64 t, %1; cvt.u32.u64 %0, t; }"
        : "=r"(a) : "l"(p));
    return a;
}
__device__ __forceinline__ void ldsm4(uint32_t* r, uint32_t a) {
    asm volatile("ldmatrix.sync.aligned.m8n8.x4.shared.b16 {%0,%1,%2,%3}, [%4];"
                 : "=r"(r[0]), "=r"(r[1]), "=r"(r[2]), "=r"(r[3]) : "r"(a));
}
__device__ __forceinline__ void mma_bf16(float* c, const uint32_t* a,
                                         const uint32_t* b) {
    asm volatile("mma.sync.aligned.m16n8k16.row.col.f32.bf16.bf16.f32 "
                 "{%0,%1,%2,%3}, {%4,%5,%6,%7}, {%8,%9}, {%0,%1,%2,%3};"
                 : "+f"(c[0]), "+f"(c[1]), "+f"(c[2]), "+f"(c[3])
                 : "r"(a[0]), "r"(a[1]), "r"(a[2]), "r"(a[3]),
                   "r"(b[0]), "r"(b[1]));
}
__device__ __forceinline__ void cp16(uint32_t sa, const void* ga) {
    asm volatile("cp.async.cg.shared.global [%0], [%1], 16;"
                 :: "r"(sa), "l"(__cvta_generic_to_global(ga)) : "memory");
}
#define CP_COMMIT() asm volatile("cp.async.commit_group;" ::: "memory")
#define CP_WAIT(n)  asm volatile("cp.async.wait_group %0;" :: "n"(n) : "memory")

// fast tanh: 1 - 2/(exp(2u)+1). abs err ~3e-7.
__device__ __forceinline__ float ftanh(float u) {
    float e = __expf(2.0f * u);
    return 1.0f - __fdividef(2.0f, e + 1.0f);
}

__global__ __launch_bounds__(512, 1)
void bvp_mma_kernel(const float* __restrict__ gx, const float* __restrict__ gy,
                    const float* __restrict__ gz, const float* __restrict__ gf,
                    const float* __restrict__ W1, const float* __restrict__ b1,
                    const float* __restrict__ b2, const float* __restrict__ b3,
                    const float* __restrict__ W4, const float* __restrict__ b4,
                    float* __restrict__ out, int N)
{
    extern __shared__ char sm[];
    const uint32_t smb = smem_u32(sm);
    float* Dst  = (float*)(sm + A_OFF);       // aliases A region, row-for-row
    float* xyzf = (float*)(sm + XYZF_OFF);
    float* part = (float*)(sm + PART_OFF);    // [16][8][4]

    const int tid = threadIdx.x;
    const int wid = tid >> 5;                 // 16 warps, n-slice wid*16
    const int lid = tid & 31;
    const int n0w = wid << 4;
    const int n0  = blockIdx.x * SB;
    const int cp  = tid & 127;                // column pair (cols 2cp, 2cp+1)
    const int qtr = tid >> 7;                 // sample quarter (4 samples)

    const float CX = (float)((0.5 * 0.6) * (0.5 * 0.6));
    const float CY = (float)((0.7 * 0.6) * (0.7 * 0.6));
    const float CZ = (float)((0.7 * 0.5) * (0.7 * 0.5));

    // warp-private B slice (16 rows, double buffered), filled by this warp
    const uint32_t myb = smb + B_OFF + wid * BTOT;
    auto issue_chunk = [&](int gi) {          // gi in [0,32): layer*16 + kc
        int L = gi >> 4, kc = gi & 15;
        uint32_t base = myb + (gi & 1) * BSTG;
        #pragma unroll
        for (int j = 0; j < 2; ++j) {
            int idx = lid + (j << 5);         // 0..63
            int r = idx >> 2, q = idx & 3;
            int split = q >> 1, half = q & 1;
            cp16(base + r * BROW + split * 32 + half * 16,
                 &Wbf[L][split][n0w + r][kc * 16 + half * 8]);
        }
        CP_COMMIT();
    };

    // packed store of a column pair (hi word + lo word)
    auto storeA2 = [&](int m, float v0, float v1) {
        __nv_bfloat16 h0 = __float2bfloat16(v0);
        __nv_bfloat16 h1 = __float2bfloat16(v1);
        __nv_bfloat16 l0 = __float2bfloat16(v0 - __bfloat162float(h0));
        __nv_bfloat16 l1 = __float2bfloat16(v1 - __bfloat162float(h1));
        uint32_t wh = (uint32_t)__bfloat16_as_ushort(h0) |
                      ((uint32_t)__bfloat16_as_ushort(h1) << 16);
        uint32_t wl = (uint32_t)__bfloat16_as_ushort(l0) |
                      ((uint32_t)__bfloat16_as_ushort(l1) << 16);
        char* base = sm + A_OFF + m * AROW + cp * 4;
        *(uint32_t*)(base)       = wh;
        *(uint32_t*)(base + 528) = wl;
    };

    // prologue: prefetch chunks 0,1 of layer 0 (per warp, private)
    issue_chunk(0);
    issue_chunk(1);

    // coords
    if (tid < 64) {
        int ss = tid >> 2, w = tid & 3;
        int n = n0 + ss; if (n >= N) n = N - 1;
        const float* p = (w == 0) ? gx : (w == 1) ? gy : (w == 2) ? gz : gf;
        xyzf[tid] = p[n];
    }
    __syncthreads();

    // ---- layer 1: 4 -> 256, jets analytically (column-pair packed) ---------
    {
        float4 w0 = *(const float4*)(W1 + (cp * 2) * 4);
        float4 w1 = *(const float4*)(W1 + (cp * 2 + 1) * 4);
        float2 bv = *(const float2*)(b1 + cp * 2);
        float g0 = CX * w0.x * w0.x + CY * w0.y * w0.y + CZ * w0.z * w0.z;
        float g1 = CX * w1.x * w1.x + CY * w1.y * w1.y + CZ * w1.z * w1.z;
        #pragma unroll
        for (int s4 = 0; s4 < 4; ++s4) {
            int s = qtr * 4 + s4;
            float xs = xyzf[s * 4 + 0], ys = xyzf[s * 4 + 1];
            float zs = xyzf[s * 4 + 2], fs = xyzf[s * 4 + 3];
            float u0 = fmaf(w0.x, xs, fmaf(w0.y, ys, fmaf(w0.z, zs,
                       fmaf(w0.w, fs, bv.x))));
            float u1 = fmaf(w1.x, xs, fmaf(w1.y, ys, fmaf(w1.z, zs,
                       fmaf(w1.w, fs, bv.y))));
            float y0 = ftanh(u0), y1 = ftanh(u1);
            float s0 = fmaf(-y0, y0, 1.0f), s1 = fmaf(-y1, y1, 1.0f);
            int m = s * 5;
            storeA2(m + 0, y0, y1);
            storeA2(m + 1, s0 * w0.x, s1 * w1.x);
            storeA2(m + 2, s0 * w0.y, s1 * w1.y);
            storeA2(m + 3, s0 * w0.z, s1 * w1.z);
            storeA2(m + 4, -2.0f * y0 * s0 * g0, -2.0f * y1 * s1 * g1);
        }
    }
    __syncthreads();

    const int g = lid >> 2, cc = (lid & 3) << 1;

    // ---- hidden layers 2,3 (zero-sync mainloop) -----------------------------
    #pragma unroll 1
    for (int L = 0; L < 2; ++L) {
        float acc[5][2][4];
        #pragma unroll
        for (int mt = 0; mt < 5; ++mt)
            #pragma unroll
            for (int nt = 0; nt < 2; ++nt)
                #pragma unroll
                for (int r = 0; r < 4; ++r) acc[mt][nt][r] = 0.f;

        #pragma unroll 1
        for (int kc = 0; kc < 16; ++kc) {     // k16 chunks
            int gi = (L << 4) | kc;
            if (gi == 31) { CP_WAIT(0); } else { CP_WAIT(1); }
            uint32_t bbase = myb + (gi & 1) * BSTG;

            // one ldsm4 per nt fetches hi (regs 0,1) AND lo (regs 2,3)
            uint32_t bf[2][4];
            #pragma unroll
            for (int nt = 0; nt < 2; ++nt) {
                uint32_t ba = bbase + ((nt << 3) + (lid & 7)) * BROW +
                              (lid & 8) * 2 + ((lid >> 4) << 5);
                ldsm4(bf[nt], ba);
            }
            #pragma unroll
            for (int mt = 0; mt < 5; ++mt) {
                int row = (mt << 4) + (lid & 15);
                uint32_t aa = smb + A_OFF + row * AROW +
                              (kc * 16 + ((lid >> 4) << 3)) * 2;
                uint32_t ah[4], al[4];
                ldsm4(ah, aa);
                ldsm4(al, aa + 528);
                #pragma unroll
                for (int nt = 0; nt < 2; ++nt) {
                    mma_bf16(acc[mt][nt], ah, &bf[nt][0]);  // hi*hi
                    mma_bf16(acc[mt][nt], al, &bf[nt][0]);  // lo*hi
                    mma_bf16(acc[mt][nt], ah, &bf[nt][2]);  // hi*lo
                }
            }
            if (gi + 2 < 32) issue_chunk(gi + 2);
        }
        __syncthreads();   // all MMA reads of A done before D overwrites A

        // ---- stage acc into D (aliases dead A rows) --------------------------
        #pragma unroll
        for (int mt = 0; mt < 5; ++mt)
            #pragma unroll
            for (int nt = 0; nt < 2; ++nt) {
                int m0 = (mt << 4), nc = n0w + (nt << 3) + cc;
                *(float2*)(Dst + (m0 + g) * DROW + nc) =
                    make_float2(acc[mt][nt][0], acc[mt][nt][1]);
                *(float2*)(Dst + (m0 + g + 8) * DROW + nc) =
                    make_float2(acc[mt][nt][2], acc[mt][nt][3]);
            }
        __syncthreads();

        // ---- activation epilogue --------------------------------------------
        if (L == 0) {
            // in-place D -> new A exchange, column-pair packed, 2 batches of
            // 2 samples per thread (disjoint rows across batches)
            float2 bn2 = *(const float2*)(b2 + cp * 2);
            #pragma unroll
            for (int bb = 0; bb < 2; ++bb) {
                float2 t5[2][5];
                #pragma unroll
                for (int j = 0; j < 2; ++j) {
                    int mr = (qtr * 4 + bb * 2 + j) * 5;
                    #pragma unroll
                    for (int ch = 0; ch < 5; ++ch)
                        t5[j][ch] = *(float2*)(Dst + (mr + ch) * DROW + cp * 2);
                }
                __syncthreads();           // all reads of these rows done
                #pragma unroll
                for (int j = 0; j < 2; ++j) {
                    int mr = (qtr * 4 + bb * 2 + j) * 5;
                    float y0 = ftanh(t5[j][0].x + bn2.x);
                    float y1 = ftanh(t5[j][0].y + bn2.y);
                    float s0 = fmaf(-y0, y0, 1.0f);
                    float s1 = fmaf(-y1, y1, 1.0f);
                    float g0 = CX * t5[j][1].x * t5[j][1].x +
                               CY * t5[j][2].x * t5[j][2].x +
                               CZ * t5[j][3].x * t5[j][3].x;
                    float g1 = CX * t5[j][1].y * t5[j][1].y +
                               CY * t5[j][2].y * t5[j][2].y +
                               CZ * t5[j][3].y * t5[j][3].y;
                    storeA2(mr + 0, y0, y1);
                    storeA2(mr + 1, s0 * t5[j][1].x, s1 * t5[j][1].y);
                    storeA2(mr + 2, s0 * t5[j][2].x, s1 * t5[j][2].y);
                    storeA2(mr + 3, s0 * t5[j][3].x, s1 * t5[j][3].y);
                    storeA2(mr + 4,
                            fmaf(s0, t5[j][4].x, -2.0f * y0 * s0 * g0),
                            fmaf(s1, t5[j][4].y, -2.0f * y1 * s1 * g1));
                }
            }
            __syncthreads();
        } else {
            const int col = tid & 255;
            const int g2  = tid >> 8;          // 8 samples each
            float bn  = b3[col];
            float w40 = W4[col], w41 = W4[HD + col];
            #pragma unroll 1
            for (int sl = 0; sl < 8; ++sl) {
                int s = g2 * 8 + sl, mr = s * 5;
                float u  = Dst[(mr + 0) * DROW + col] + bn;
                float tx = Dst[(mr + 1) * DROW + col];
                float ty = Dst[(mr + 2) * DROW + col];
                float tz = Dst[(mr + 3) * DROW + col];
                float qa = Dst[(mr + 4) * DROW + col];
                float yv = ftanh(u);
                float sgm = fmaf(-yv, yv, 1.0f);
                float gq = CX * tx * tx + CY * ty * ty + CZ * tz * tz;
                float qn = fmaf(sgm, qa, -2.0f * yv * sgm * gq);
                float v0 = w40 * yv, v1 = w41 * yv;
                float v2 = w40 * qn, v3 = w41 * qn;
                #pragma unroll
                for (int o = 16; o; o >>= 1) {
                    v0 += __shfl_xor_sync(0xFFFFFFFFu, v0, o);
                    v1 += __shfl_xor_sync(0xFFFFFFFFu, v1, o);
                    v2 += __shfl_xor_sync(0xFFFFFFFFu, v2, o);
                    v3 += __shfl_xor_sync(0xFFFFFFFFu, v3, o);
                }
                if (lid == 0) {
                    float* pp = part + (s * 8 + (wid & 7)) * 4;
                    pp[0] = v0; pp[1] = v1; pp[2] = v2; pp[3] = v3;
                }
            }
            __syncthreads();
        }
    }

    // ---- residual output -----------------------------------------------------
    if (tid < SB) {
        int n = n0 + tid;
        if (n < N) {
            float P0 = 0.f, P1 = 0.f, Q0 = 0.f, Q1 = 0.f;
            #pragma unroll
            for (int w = 0; w < 8; ++w) {
                const float* pp = part + (tid * 8 + w) * 4;
                P0 += pp[0]; P1 += pp[1]; Q0 += pp[2]; Q1 += pp[3];
            }
            P0 += b4[0]; P1 += b4[1];
            float fs = xyzf[tid * 4 + 3];
            float kw = 6.283185307179586f * fmaf(fs, 500.0f, 100.0f) / 343.0f;
            float kx = 0.21f * kw;
            float K2 = kx * kx;
            out[n]     = 2.0f * Q0 + K2 * fmaf(2.0f, P0, 0.1f);
            out[N + n] = 1.5f * Q1 + K2 * fmaf(1.5f, P1, -0.05f);
        }
    }
}

extern "C" void kernel_launch(void* const* d_in, const int* in_sizes, int n_in,
                              void* d_out, int out_size)
{
    const float* x  = (const float*)d_in[0];
    const float* y  = (const float*)d_in[1];
    const float* z  = (const float*)d_in[2];
    const float* f  = (const float*)d_in[3];
    const float* W1 = (const float*)d_in[4];
    const float* b1 = (const float*)d_in[5];
    const float* W2 = (const float*)d_in[6];
    const float* b2 = (const float*)d_in[7];
    const float* W3 = (const float*)d_in[8];
    const float* b3 = (const float*)d_in[9];
    const float* W4 = (const float*)d_in[10];
    const float* b4 = (const float*)d_in[11];
    float* out = (float*)d_out;

    int N = in_sizes[0];
    prep_weights<<<512, 256>>>(W2, W3);

    cudaFuncSetAttribute(bvp_mma_kernel,
                         cudaFuncAttributeMaxDynamicSharedMemorySize,
                         SMEM_BYTES);
    int blocks = (N + SB - 1) / SB;
    bvp_mma_kernel<<<blocks, 512, SMEM_BYTES>>>(x, y, z, f, W1, b1, b2, b3,
                                                W4, b4, out, N);
}

// round 16
// speedup vs baseline: 3.0628x; 1.1767x over previous
#include <cuda_runtime.h>
#include <cuda_bf16.h>
#include <cstdint>

// ---------------------------------------------------------------------------
// BVP Helmholtz residual via 2nd-order jet propagation on mma.sync bf16 HMMA
// (3-pass hi/lo split). Round 16: M=160 (32 samples/CTA, ZERO pad waste),
// 512 thr / 16 warps = 2 m-groups(80 rows) x 8 n-slices(32 cols), each warp
// mt5 x nt4 (60 MMAs per k16 chunk). B pair-shared, double-buffered k16
// slices filled by the mg0 warp, pair-synced with 64-thread named barriers.
// Combined hi/lo B ldsm4. D aliases dead A rows (in-place jet exchange).
// ---------------------------------------------------------------------------

#define HD 256
#define SB 32              // samples per CTA (160 jet rows, M=160)
#define AROW 1040          // A row bytes: hi[0,512) pad lo[528,1040) == D row
#define DROW 260           // D row stride in floats (= 1040 B)
#define BROW 80            // B slice row: hi k16 (32B) + lo k16 (32B) + pad
#define BSTG 2560          // 32 rows * 80 = one stage of one pair's slice
#define BTOT 5120          // 2 stages

#define A_OFF 0            // 160*1040 = 166400
#define B_OFF 166400       // 8 slices * 5120 = 40960
#define XYZF_OFF 207360    // 32*4*4 = 512
#define PART_OFF 207872    // 32*8*4*4 = 4096
#define SMEM_BYTES 211968

// prepped weights: [layer][split hi/lo][n][k] bf16
__device__ __align__(16) __nv_bfloat16 Wbf[2][2][HD][HD];

__global__ __launch_bounds__(256)
void prep_weights(const float* __restrict__ W2, const float* __restrict__ W3)
{
    int t = blockIdx.x * 256 + threadIdx.x;      // 131072
    int layer = t >> 16, n = (t >> 8) & 255, k = t & 255;
    float w = (layer ? W3 : W2)[n * HD + k];
    __nv_bfloat16 h = __float2bfloat16(w);
    __nv_bfloat16 l = __float2bfloat16(w - __bfloat162float(h));
    Wbf[layer][0][n][k] = h;
    Wbf[layer][1][n][k] = l;
}

__device__ __forceinline__ uint32_t smem_u32(const void* p) {
    uint32_t a;
    asm("{ .reg .u64 t; cvta.to.shared.u64 t, %1; cvt.u32.u64 %0, t; }"
        : "=r"(a) : "l"(p));
    return a;
}
__device__ __forceinline__ void ldsm4(uint32_t* r, uint32_t a) {
    asm volatile("ldmatrix.sync.aligned.m8n8.x4.shared.b16 {%0,%1,%2,%3}, [%4];"
                 : "=r"(r[0]), "=r"(r[1]), "=r"(r[2]), "=r"(r[3]) : "r"(a));
}
__device__ __forceinline__ void mma_bf16(float* c, const uint32_t* a,
                                         const uint32_t* b) {
    asm volatile("mma.sync.aligned.m16n8k16.row.col.f32.bf16.bf16.f32 "
                 "{%0,%1,%2,%3}, {%4,%5,%6,%7}, {%8,%9}, {%0,%1,%2,%3};"
                 : "+f"(c[0]), "+f"(c[1]), "+f"(c[2]), "+f"(c[3])
                 : "r"(a[0]), "r"(a[1]), "r"(a[2]), "r"(a[3]),
                   "r"(b[0]), "r"(b[1]));
}
__device__ __forceinline__ void cp16(uint32_t sa, const void* ga) {
    asm volatile("cp.async.cg.shared.global [%0], [%1], 16;"
                 :: "r"(sa), "l"(__cvta_generic_to_global(ga)) : "memory");
}
#define CP_COMMIT() asm volatile("cp.async.commit_group;" ::: "memory")
#define CP_WAIT(n)  asm volatile("cp.async.wait_group %0;" :: "n"(n) : "memory")
#define PAIR_BAR(id) asm volatile("bar.sync %0, 64;" :: "r"(id) : "memory")

// fast tanh: 1 - 2/(exp(2u)+1). abs err ~3e-7.
__device__ __forceinline__ float ftanh(float u) {
    float e = __expf(2.0f * u);
    return 1.0f - __fdividef(2.0f, e + 1.0f);
}

__global__ __launch_bounds__(512, 1)
void bvp_mma_kernel(const float* __restrict__ gx, const float* __restrict__ gy,
                    const float* __restrict__ gz, const float* __restrict__ gf,
                    const float* __restrict__ W1, const float* __restrict__ b1,
                    const float* __restrict__ b2, const float* __restrict__ b3,
                    const float* __restrict__ W4, const float* __restrict__ b4,
                    float* __restrict__ out, int N)
{
    extern __shared__ char sm[];
    const uint32_t smb = smem_u32(sm);
    float* Dst  = (float*)(sm + A_OFF);       // aliases A region, row-for-row
    float* xyzf = (float*)(sm + XYZF_OFF);
    float* part = (float*)(sm + PART_OFF);    // [32][8][4]

    const int tid = threadIdx.x;
    const int wid = tid >> 5;
    const int lid = tid & 31;
    const int mg  = wid >> 3;                 // m-group (rows mg*80..+80)
    const int ng  = wid & 7;                  // n-slice (cols ng*32..+32)
    const int n0w = ng << 5;
    const int n0  = blockIdx.x * SB;
    const int cp  = tid & 127;                // column pair (cols 2cp, 2cp+1)
    const int qtr = tid >> 7;                 // 4 groups x 8 samples

    const float CX = (float)((0.5 * 0.6) * (0.5 * 0.6));
    const float CY = (float)((0.7 * 0.6) * (0.7 * 0.6));
    const float CZ = (float)((0.7 * 0.5) * (0.7 * 0.5));

    // pair-shared B slice (32 rows, double buffered); mg0 warp fills it.
    const uint32_t pairb = smb + B_OFF + ng * BTOT;
    auto issue_chunk = [&](int gi) {          // gi in [0,32): layer*16 + kc
        int L = gi >> 4, kc = gi & 15;
        uint32_t base = pairb + (gi & 1) * BSTG;
        #pragma unroll
        for (int j = 0; j < 4; ++j) {
            int idx = lid + (j << 5);         // 0..127
            int r = idx >> 2, q = idx & 3;
            int split = q >> 1, half = q & 1;
            cp16(base + r * BROW + split * 32 + half * 16,
                 &Wbf[L][split][n0w + r][kc * 16 + half * 8]);
        }
        CP_COMMIT();
    };

    // packed store of a column pair (hi word + lo word)
    auto storeA2 = [&](int m, float v0, float v1) {
        __nv_bfloat16 h0 = __float2bfloat16(v0);
        __nv_bfloat16 h1 = __float2bfloat16(v1);
        __nv_bfloat16 l0 = __float2bfloat16(v0 - __bfloat162float(h0));
        __nv_bfloat16 l1 = __float2bfloat16(v1 - __bfloat162float(h1));
        uint32_t wh = (uint32_t)__bfloat16_as_ushort(h0) |
                      ((uint32_t)__bfloat16_as_ushort(h1) << 16);
        uint32_t wl = (uint32_t)__bfloat16_as_ushort(l0) |
                      ((uint32_t)__bfloat16_as_ushort(l1) << 16);
        char* base = sm + A_OFF + m * AROW + cp * 4;
        *(uint32_t*)(base)       = wh;
        *(uint32_t*)(base + 528) = wl;
    };

    // prologue: mg0 prefetches chunks 0,1 of layer 0
    if (mg == 0) { issue_chunk(0); issue_chunk(1); }

    // coords
    if (tid < 128) {
        int ss = tid >> 2, w = tid & 3;
        int n = n0 + ss; if (n >= N) n = N - 1;
        const float* p = (w == 0) ? gx : (w == 1) ? gy : (w == 2) ? gz : gf;
        xyzf[tid] = p[n];
    }
    __syncthreads();

    // ---- layer 1: 4 -> 256, jets analytically (column-pair packed) ---------
    {
        float4 w0 = *(const float4*)(W1 + (cp * 2) * 4);
        float4 w1 = *(const float4*)(W1 + (cp * 2 + 1) * 4);
        float2 bv = *(const float2*)(b1 + cp * 2);
        float g0 = CX * w0.x * w0.x + CY * w0.y * w0.y + CZ * w0.z * w0.z;
        float g1 = CX * w1.x * w1.x + CY * w1.y * w1.y + CZ * w1.z * w1.z;
        #pragma unroll 1
        for (int s8 = 0; s8 < 8; ++s8) {
            int s = qtr * 8 + s8;
            float xs = xyzf[s * 4 + 0], ys = xyzf[s * 4 + 1];
            float zs = xyzf[s * 4 + 2], fs = xyzf[s * 4 + 3];
            float u0 = fmaf(w0.x, xs, fmaf(w0.y, ys, fmaf(w0.z, zs,
                       fmaf(w0.w, fs, bv.x))));
            float u1 = fmaf(w1.x, xs, fmaf(w1.y, ys, fmaf(w1.z, zs,
                       fmaf(w1.w, fs, bv.y))));
            float y0 = ftanh(u0), y1 = ftanh(u1);
            float s0 = fmaf(-y0, y0, 1.0f), s1 = fmaf(-y1, y1, 1.0f);
            int m = s * 5;
            storeA2(m + 0, y0, y1);
            storeA2(m + 1, s0 * w0.x, s1 * w1.x);
            storeA2(m + 2, s0 * w0.y, s1 * w1.y);
            storeA2(m + 3, s0 * w0.z, s1 * w1.z);
            storeA2(m + 4, -2.0f * y0 * s0 * g0, -2.0f * y1 * s1 * g1);
        }
    }
    __syncthreads();

    const int g = lid >> 2, cc = (lid & 3) << 1;

    // ---- hidden layers 2,3 --------------------------------------------------
    #pragma unroll 1
    for (int L = 0; L < 2; ++L) {
        float acc[5][4][4];
        #pragma unroll
        for (int mt = 0; mt < 5; ++mt)
            #pragma unroll
            for (int nt = 0; nt < 4; ++nt)
                #pragma unroll
                for (int r = 0; r < 4; ++r) acc[mt][nt][r] = 0.f;

        #pragma unroll 1
        for (int kc = 0; kc < 16; ++kc) {     // k16 chunks
            int gi = (L << 4) | kc;
            // pair pipeline: mg0 lands data; barrier also proves both warps
            // finished chunk gi-1 (buffer (gi+1)&1) before refill
            if (mg == 0) { if (gi == 31) CP_WAIT(0); else CP_WAIT(1); }
            PAIR_BAR(ng + 1);
            if (mg == 0 && gi + 1 < 32) issue_chunk(gi + 1);

            uint32_t bbase = pairb + (gi & 1) * BSTG;
            // one ldsm4 per nt fetches hi (regs 0,1) AND lo (regs 2,3)
            uint32_t bf[4][4];
            #pragma unroll
            for (int nt = 0; nt < 4; ++nt) {
                uint32_t ba = bbase + ((nt << 3) + (lid & 7)) * BROW +
                              (lid & 8) * 2 + ((lid >> 4) << 5);
                ldsm4(bf[nt], ba);
            }
            #pragma unroll
            for (int mt = 0; mt < 5; ++mt) {
                int row = mg * 80 + (mt << 4) + (lid & 15);
                uint32_t aa = smb + A_OFF + row * AROW +
                              (kc * 16 + ((lid >> 4) << 3)) * 2;
                uint32_t ah[4], al[4];
                ldsm4(ah, aa);
                ldsm4(al, aa + 528);
                #pragma unroll
                for (int nt = 0; nt < 4; ++nt) {
                    mma_bf16(acc[mt][nt], ah, &bf[nt][0]);  // hi*hi
                    mma_bf16(acc[mt][nt], al, &bf[nt][0]);  // lo*hi
                    mma_bf16(acc[mt][nt], ah, &bf[nt][2]);  // hi*lo
                }
            }
        }
        __syncthreads();   // all MMA reads of A done before D overwrites A

        // ---- stage acc into D (aliases dead A rows) --------------------------
        #pragma unroll
        for (int mt = 0; mt < 5; ++mt)
            #pragma unroll
            for (int nt = 0; nt < 4; ++nt) {
                int m0 = mg * 80 + (mt << 4), nc = n0w + (nt << 3) + cc;
                *(float2*)(Dst + (m0 + g) * DROW + nc) =
                    make_float2(acc[mt][nt][0], acc[mt][nt][1]);
                *(float2*)(Dst + (m0 + g + 8) * DROW + nc) =
                    make_float2(acc[mt][nt][2], acc[mt][nt][3]);
            }
        __syncthreads();

        // ---- activation epilogue --------------------------------------------
        if (L == 0) {
            // in-place D -> new A exchange, column-pair packed,
            // 4 batches of 2 samples per thread group
            float2 bn2 = *(const float2*)(b2 + cp * 2);
            #pragma unroll 1
            for (int bb = 0; bb < 4; ++bb) {
                float2 t5[2][5];
                #pragma unroll
                for (int j = 0; j < 2; ++j) {
                    int mr = (qtr * 8 + bb * 2 + j) * 5;
                    #pragma unroll
                    for (int ch = 0; ch < 5; ++ch)
                        t5[j][ch] = *(float2*)(Dst + (mr + ch) * DROW + cp * 2);
                }
                __syncthreads();           // all reads of these rows done
                #pragma unroll
                for (int j = 0; j < 2; ++j) {
                    int mr = (qtr * 8 + bb * 2 + j) * 5;
                    float y0 = ftanh(t5[j][0].x + bn2.x);
                    float y1 = ftanh(t5[j][0].y + bn2.y);
                    float s0 = fmaf(-y0, y0, 1.0f);
                    float s1 = fmaf(-y1, y1, 1.0f);
                    float g0 = CX * t5[j][1].x * t5[j][1].x +
                               CY * t5[j][2].x * t5[j][2].x +
                               CZ * t5[j][3].x * t5[j][3].x;
                    float g1 = CX * t5[j][1].y * t5[j][1].y +
                               CY * t5[j][2].y * t5[j][2].y +
                               CZ * t5[j][3].y * t5[j][3].y;
                    storeA2(mr + 0, y0, y1);
                    storeA2(mr + 1, s0 * t5[j][1].x, s1 * t5[j][1].y);
                    storeA2(mr + 2, s0 * t5[j][2].x, s1 * t5[j][2].y);
                    storeA2(mr + 3, s0 * t5[j][3].x, s1 * t5[j][3].y);
                    storeA2(mr + 4,
                            fmaf(s0, t5[j][4].x, -2.0f * y0 * s0 * g0),
                            fmaf(s1, t5[j][4].y, -2.0f * y1 * s1 * g1));
                }
            }
            __syncthreads();
        } else {
            const int col = tid & 255;
            const int g2  = tid >> 8;          // 16 samples each
            float bn  = b3[col];
            float w40 = W4[col], w41 = W4[HD + col];
            #pragma unroll 1
            for (int sl = 0; sl < 16; ++sl) {
                int s = g2 * 16 + sl, mr = s * 5;
                float u  = Dst[(mr + 0) * DROW + col] + bn;
                float tx = Dst[(mr + 1) * DROW + col];
                float ty = Dst[(mr + 2) * DROW + col];
                float tz = Dst[(mr + 3) * DROW + col];
                float qa = Dst[(mr + 4) * DROW + col];
                float yv = ftanh(u);
                float sgm = fmaf(-yv, yv, 1.0f);
                float gq = CX * tx * tx + CY * ty * ty + CZ * tz * tz;
                float qn = fmaf(sgm, qa, -2.0f * yv * sgm * gq);
                float v0 = w40 * yv, v1 = w41 * yv;
                float v2 = w40 * qn, v3 = w41 * qn;
                #pragma unroll
                for (int o = 16; o; o >>= 1) {
                    v0 += __shfl_xor_sync(0xFFFFFFFFu, v0, o);
                    v1 += __shfl_xor_sync(0xFFFFFFFFu, v1, o);
                    v2 += __shfl_xor_sync(0xFFFFFFFFu, v2, o);
                    v3 += __shfl_xor_sync(0xFFFFFFFFu, v3, o);
                }
                if (lid == 0) {
                    float* pp = part + (s * 8 + (wid & 7)) * 4;
                    pp[0] = v0; pp[1] = v1; pp[2] = v2; pp[3] = v3;
                }
            }
            __syncthreads();
        }
    }

    // ---- residual output -----------------------------------------------------
    if (tid < SB) {
        int n = n0 + tid;
        if (n < N) {
            float P0 = 0.f, P1 = 0.f, Q0 = 0.f, Q1 = 0.f;
            #pragma unroll
            for (int w = 0; w < 8; ++w) {
                const float* pp = part + (tid * 8 + w) * 4;
                P0 += pp[0]; P1 += pp[1]; Q0 += pp[2]; Q1 += pp[3];
            }
            P0 += b4[0]; P1 += b4[1];
            float fs = xyzf[tid * 4 + 3];
            float kw = 6.283185307179586f * fmaf(fs, 500.0f, 100.0f) / 343.0f;
            float kx = 0.21f * kw;
            float K2 = kx * kx;
            out[n]     = 2.0f * Q0 + K2 * fmaf(2.0f, P0, 0.1f);
            out[N + n] = 1.5f * Q1 + K2 * fmaf(1.5f, P1, -0.05f);
        }
    }
}

extern "C" void kernel_launch(void* const* d_in, const int* in_sizes, int n_in,
                              void* d_out, int out_size)
{
    const float* x  = (const float*)d_in[0];
    const float* y  = (const float*)d_in[1];
    const float* z  = (const float*)d_in[2];
    const float* f  = (const float*)d_in[3];
    const float* W1 = (const float*)d_in[4];
    const float* b1 = (const float*)d_in[5];
    const float* W2 = (const float*)d_in[6];
    const float* b2 = (const float*)d_in[7];
    const float* W3 = (const float*)d_in[8];
    const float* b3 = (const float*)d_in[9];
    const float* W4 = (const float*)d_in[10];
    const float* b4 = (const float*)d_in[11];
    float* out = (float*)d_out;

    int N = in_sizes[0];
    prep_weights<<<512, 256>>>(W2, W3);

    cudaFuncSetAttribute(bvp_mma_kernel,
                         cudaFuncAttributeMaxDynamicSharedMemorySize,
                         SMEM_BYTES);
    int blocks = (N + SB - 1) / SB;
    bvp_mma_kernel<<<blocks, 512, SMEM_BYTES>>>(x, y, z, f, W1, b1, b2, b3,
                                                W4, b4, out, N);
}